// round 13
// baseline (speedup 1.0000x reference)
#include <cuda_runtime.h>
#include <cuda_bf16.h>

// SSIM loss: X,Y (32,8,320,320) fp32, 7x7 uniform box (valid), out = 1 - mean(S)
//
// Barrier-free warp-fused design (no SMEM staging):
//  - warp owns a 32-col span; lane = column (coalesced LDG, 1 line/load)
//  - vertical 7-row running sums per lane, static 6-deep register ring
//  - horizontal 7-window via lane shuffles: W7(c)=t4(c)+s1(c+4)+E(c+6)
//    (d1,d2,d4,d6 -> 8 SHFL + 4 f2add per packed quantity; adds only, no
//    cancellation). Lanes 0..25 emit outputs.
//  - 13 col-spans x 9 row-strips(36) x 256 imgs = 29952 warp-tasks, 4/block
//  - one-row software prefetch; zero __syncthreads in the hot path

#define WIN     7
#define IMG     320
#define OUT     314
#define NIMG    256
#define NELEM   25240576.0

#define CSPAN   26                   // output cols per warp
#define NCS     13                   // col spans  (13*26 = 338 >= 314)
#define RSTRIP  36                   // output rows per warp task
#define NRS     9                    // row strips (9*36 = 324 >= 314)
#define NSPAN   (NCS * NRS)          // 117
#define WPB     4                    // warps per block
#define GRID_X  ((NSPAN + WPB - 1) / WPB)   // 30
#define NBLOCKS (GRID_X * NIMG)             // 7680

__device__ double g_accum;
__device__ unsigned int g_count;

// ---- packed f32x2 helpers (sm_103a) ----
__device__ __forceinline__ float2 f2add(float2 a, float2 b) {
    unsigned long long ra = *(unsigned long long*)&a;
    unsigned long long rb = *(unsigned long long*)&b;
    unsigned long long rd;
    asm("add.rn.f32x2 %0, %1, %2;" : "=l"(rd) : "l"(ra), "l"(rb));
    return *(float2*)&rd;
}
__device__ __forceinline__ float2 f2mul(float2 a, float2 b) {
    unsigned long long ra = *(unsigned long long*)&a;
    unsigned long long rb = *(unsigned long long*)&b;
    unsigned long long rd;
    asm("mul.rn.f32x2 %0, %1, %2;" : "=l"(rd) : "l"(ra), "l"(rb));
    return *(float2*)&rd;
}
__device__ __forceinline__ float2 f2fma(float2 a, float2 b, float2 c) {
    unsigned long long ra = *(unsigned long long*)&a;
    unsigned long long rb = *(unsigned long long*)&b;
    unsigned long long rc = *(unsigned long long*)&c;
    unsigned long long rd;
    asm("fma.rn.f32x2 %0, %1, %2, %3;" : "=l"(rd) : "l"(ra), "l"(rb), "l"(rc));
    return *(float2*)&rd;
}
__device__ __forceinline__ float2 shdown2(float2 v, int d) {
    float2 r;
    r.x = __shfl_down_sync(0xffffffffu, v.x, d);
    r.y = __shfl_down_sync(0xffffffffu, v.y, d);
    return r;
}

__global__ __launch_bounds__(128) void ssim_main_kernel(
    const float* __restrict__ X, const float* __restrict__ Y,
    const float* __restrict__ data_range, const float* __restrict__ w,
    float* __restrict__ out)
{
    __shared__ float warpsum[WPB];

    const int tid  = threadIdx.x;
    const int wid  = tid >> 5;
    const int lane = tid & 31;
    const int sid  = blockIdx.x * WPB + wid;    // warp task id
    const int img  = blockIdx.y;

    // SSIM constants (rescaled by (1/w)^2 so no per-pixel weight mults)
    const float w0  = w[0];
    const float iw  = 1.0f / w0;                // ~49
    const float dr  = data_range[0];
    const float c1t = 0.01f * dr;
    const float c2t = 0.03f * dr;
    const float C1s = (c1t * c1t) * iw * iw;
    const float C2s = (c2t * c2t) * iw * iw;
    const float COV  = 49.0f / 48.0f;
    const float COV2 = 2.0f * COV;
    const float epsS = 1e-8f * (iw * iw) * (iw * iw);
    const float2 neg1 = make_float2(-1.f, -1.f);

    float local = 0.f;

    if (sid < NSPAN) {
        const int cs = sid % NCS;
        const int rs = sid / NCS;
        const int oc = cs * CSPAN + lane;           // this lane's output col
        const int gx = min(oc, IMG - 1);            // clamped cols feed only
                                                    // masked outputs
        const int r0 = rs * RSTRIP;
        const float* xp = X + (size_t)img * IMG * IMG + gx;
        const float* yp = Y + (size_t)img * IMG * IMG + gx;
        const bool laneok = (lane < CSPAN) && (oc < OUT);

        // ---- prime: rows r0..r0+5 into ring + running sums (always in-bounds,
        //      max r0+5 = 293) ----
        float hx[6], hy[6];
        float2 P = make_float2(0.f, 0.f);           // (sx, sy) over 6 rows
        float2 Q = make_float2(0.f, 0.f);           // (sxx, syy)
        float  R = 0.f;                             // sxy
        #pragma unroll
        for (int j = 0; j < 6; j++) {
            const int off = (r0 + j) * IMG;
            const float xv = __ldg(xp + off);
            const float yv = __ldg(yp + off);
            hx[j] = xv; hy[j] = yv;
            const float2 p = make_float2(xv, yv);
            P = f2add(P, p);
            Q = f2fma(p, p, Q);
            R = fmaf(xv, yv, R);
        }
        // prefetch row r0+6 (in-bounds: max 294)
        float xn = __ldg(xp + (r0 + 6) * IMG);
        float yn = __ldg(yp + (r0 + 6) * IMG);

        // ---- main loop: 36 output rows = 6 groups x 6 (static ring slots) ----
        #pragma unroll 1
        for (int g = 0; g < 6; g++) {
            #pragma unroll
            for (int i = 0; i < 6; i++) {
                const int orow = r0 + g * 6 + i;
                // prefetch next row (clamped; clamped rows feed only masked
                // outputs, and add/sub of the same stored value keeps sums
                // consistent)
                const int offn = min(orow + 7, IMG - 1) * IMG;
                const float xf = __ldg(xp + offn);
                const float yf = __ldg(yp + offn);

                // 7-row window sums for this output row
                const float2 p  = make_float2(xn, yn);
                const float2 Pw = f2add(P, p);
                const float2 Qw = f2fma(p, p, Q);
                const float  Rw = fmaf(xn, yn, R);

                // horizontal 7-window across lanes: W7(c)=t4(c)+s1(c+4)+E(c+6)
                const float2 A = Pw;                              // (sx, sy)
                const float2 B = make_float2(Qw.x + Qw.y, Rw);    // (sqq, sxy)

                const float2 As1 = f2add(A, shdown2(A, 1));
                const float2 At4 = f2add(As1, shdown2(As1, 2));
                const float2 WA  = f2add(f2add(At4, shdown2(As1, 4)),
                                         shdown2(A, 6));
                const float2 Bs1 = f2add(B, shdown2(B, 1));
                const float2 Bt4 = f2add(Bs1, shdown2(Bs1, 2));
                const float2 WB  = f2add(f2add(Bt4, shdown2(Bs1, 4)),
                                         shdown2(B, 6));

                // SSIM (rescaled algebra)
                const float sx = WA.x, sy = WA.y;
                const float sqq = WB.x, sxy = WB.y;
                const float2 PP = f2mul(WA, WA);
                const float t1 = sx * sy;
                const float b1 = PP.x + PP.y;
                const float A1 = fmaf(t1, 2.0f, C1s);
                const float B1 = b1 + C1s;
                const float A2 = fmaf(COV2, fmaf(iw, sxy, -t1), C2s);
                const float B2 = fmaf(COV,  fmaf(iw, sqq, -b1), C2s);
                if (laneok && (orow < OUT))
                    local += __fdividef(A1 * A2, fmaf(B1, B2, epsS));

                // vertical slide: drop oldest (static slot i), insert new
                const float2 po = make_float2(hx[i], hy[i]);
                P = f2fma(po, neg1, Pw);
                const float2 mpo = f2mul(po, neg1);
                Q = f2fma(mpo, po, Qw);
                R = fmaf(-hx[i], hy[i], Rw);
                hx[i] = xn; hy[i] = yn;
                xn = xf; yn = yf;
            }
        }
    }

    // ---------------- warp + block reduction, fused finalize ----------------
    #pragma unroll
    for (int off = 16; off > 0; off >>= 1)
        local += __shfl_down_sync(0xffffffffu, local, off);
    if (lane == 0) warpsum[wid] = local;
    __syncthreads();
    if (tid == 0) {
        const float v = warpsum[0] + warpsum[1] + warpsum[2] + warpsum[3];
        atomicAdd(&g_accum, (double)v);
        __threadfence();
        const unsigned done = atomicAdd(&g_count, 1u);
        if (done == NBLOCKS - 1) {
            const double total = atomicAdd(&g_accum, 0.0);
            out[0] = (float)(1.0 - total / NELEM);
            g_accum = 0.0;            // reset for next graph replay
            g_count = 0u;
        }
    }
}

extern "C" void kernel_launch(void* const* d_in, const int* in_sizes, int n_in,
                              void* d_out, int out_size) {
    const float* X  = (const float*)d_in[0];
    const float* Y  = (const float*)d_in[1];
    const float* dr = (const float*)d_in[2];
    const float* w  = (const float*)d_in[3];
    float* out = (float*)d_out;

    dim3 grid(GRID_X, NIMG);
    ssim_main_kernel<<<grid, 128>>>(X, Y, dr, w, out);
}

// round 14
// speedup vs baseline: 1.8107x; 1.8107x over previous
#include <cuda_runtime.h>
#include <cuda_bf16.h>

// SSIM loss: X,Y (32,8,320,320) fp32, 7x7 uniform box (valid), out = 1 - mean(S)
//
// R10 skeleton (best: 80.8us): strip-mined vertical slide, float4 SMEM plane,
// chunk-of-8 phase 2 with 7-deep ring, launch_bounds(128,8).
// This round (liveness-safe instruction cuts only):
//  - hoisted per-thread column mask (iteration-invariant bounds logic)
//  - paired reciprocal: one MUFU.RCP per 2 outputs

#define WIN      7
#define IMG      320
#define OUT      314
#define NIMG     256
#define NELEM    25240576.0

#define COLS     64
#define TILE_W   58
#define STRIP    80                  // output rows per block strip
#define HALF     40                  // rows per thread-segment
#define NITER    5                   // iterations of 16 buffer rows (8 per seg)
#define SSTRIDE  (COLS + 1)          // 65 float4 entries per row
#define GRID_X   6
#define GRID_Y   4
#define NBLOCKS  (GRID_X * GRID_Y * NIMG)   // 6144

__device__ double g_accum;
__device__ unsigned int g_count;

// ---- packed f32x2 helpers (sm_103a) ----
__device__ __forceinline__ float2 f2add(float2 a, float2 b) {
    unsigned long long ra = *(unsigned long long*)&a;
    unsigned long long rb = *(unsigned long long*)&b;
    unsigned long long rd;
    asm("add.rn.f32x2 %0, %1, %2;" : "=l"(rd) : "l"(ra), "l"(rb));
    return *(float2*)&rd;
}
__device__ __forceinline__ float2 f2mul(float2 a, float2 b) {
    unsigned long long ra = *(unsigned long long*)&a;
    unsigned long long rb = *(unsigned long long*)&b;
    unsigned long long rd;
    asm("mul.rn.f32x2 %0, %1, %2;" : "=l"(rd) : "l"(ra), "l"(rb));
    return *(float2*)&rd;
}
__device__ __forceinline__ float2 f2fma(float2 a, float2 b, float2 c) {
    unsigned long long ra = *(unsigned long long*)&a;
    unsigned long long rb = *(unsigned long long*)&b;
    unsigned long long rc = *(unsigned long long*)&c;
    unsigned long long rd;
    asm("fma.rn.f32x2 %0, %1, %2, %3;" : "=l"(rd) : "l"(ra), "l"(rb), "l"(rc));
    return *(float2*)&rd;
}

__global__ __launch_bounds__(128, 8) void ssim_main_kernel(
    const float* __restrict__ X, const float* __restrict__ Y,
    const float* __restrict__ data_range, const float* __restrict__ w,
    float* __restrict__ out)
{
    __shared__ float4 s_E[16][SSTRIDE];   // (sx, sy, sxx+syy, sxy)
    __shared__ float  warpsum[4];

    const int img = blockIdx.z;
    const int tx0 = blockIdx.x * TILE_W;
    const int ty0 = blockIdx.y * STRIP;
    const float* Xb = X + (size_t)img * IMG * IMG;
    const float* Yb = Y + (size_t)img * IMG * IMG;
    const int tid = threadIdx.x;
    const float2 neg1 = make_float2(-1.f, -1.f);

    // constants for SSIM (rescaled by (1/w)^2)
    const float w0  = w[0];
    const float iw  = 1.0f / w0;                // ~49
    const float dr  = data_range[0];
    const float c1t = 0.01f * dr;
    const float c2t = 0.03f * dr;
    const float C1s = (c1t * c1t) * iw * iw;
    const float C2s = (c2t * c2t) * iw * iw;
    const float COV  = 49.0f / 48.0f;
    const float COV2 = 2.0f * COV;
    const float epsS = 1e-8f * (iw * iw) * (iw * iw);

    // phase-1 coords: thread = (column, segment)
    const int col = tid & (COLS - 1);
    const int seg = tid >> 6;                   // 0..1
    const int gx  = min(tx0 + col, IMG - 1);    // clamped cols feed only
                                                // discarded outputs
    const int base = ty0 + seg * HALF;          // first input row of segment
    const float* xp = Xb + (size_t)base * IMG + gx;
    const float* yp = Yb + (size_t)base * IMG + gx;

    // phase-2 coords
    const int r2 = tid & 15;                    // buffer row
    const int q  = tid >> 4;                    // 0..7 column chunk
    const int c0 = q * 8;

    // hoisted column mask (iteration-invariant): bit ci set if output col valid
    unsigned colmask = 0u;
    #pragma unroll
    for (int ci = 0; ci < 8; ci++) {
        const int c = c0 + ci;
        if ((c < TILE_W) && (tx0 + c < OUT)) colmask |= (1u << ci);
    }

    // prime carry: input rows base..base+5 (max base=280 -> always in-bounds)
    float cx[6], cy[6];
    #pragma unroll
    for (int j = 0; j < 6; j++) {
        cx[j] = __ldg(xp + j * IMG);
        cy[j] = __ldg(yp + j * IMG);
    }
    const float* xp2 = xp + 6 * IMG;
    const float* yp2 = yp + 6 * IMG;

    float local = 0.f;

    #pragma unroll 1
    for (int it = 0; it < NITER; ++it) {
        // ---- load 8 new input rows (front-batched for MLP) ----
        float nx[8], ny[8];
        const int rbase = base + it * 8 + 6;
        if (rbase + 7 < IMG) {                  // warp-uniform branch
            #pragma unroll
            for (int j = 0; j < 8; j++) {
                nx[j] = __ldg(xp2 + j * IMG);
                ny[j] = __ldg(yp2 + j * IMG);
            }
        } else {                                // only strip 3 / seg 1 / it 4
            #pragma unroll
            for (int j = 0; j < 8; j++) {
                const int dj = min(rbase + j, IMG - 1) - rbase;
                nx[j] = __ldg(xp2 + dj * IMG);
                ny[j] = __ldg(yp2 + dj * IMG);
            }
        }
        xp2 += 8 * IMG; yp2 += 8 * IMG;

        // ---- vertical slide over 14-row window (carry[6] + new[8]) ----
        {
            float2 P = make_float2(0.f, 0.f);
            float2 Q = make_float2(0.f, 0.f);
            float  R = 0.f;
            #pragma unroll
            for (int k = 0; k < 6; k++) {
                const float2 p = make_float2(cx[k], cy[k]);
                P = f2add(P, p);
                Q = f2fma(p, p, Q);
                R = fmaf(cx[k], cy[k], R);
            }
            {
                const float2 p = make_float2(nx[0], ny[0]);
                P = f2add(P, p);
                Q = f2fma(p, p, Q);
                R = fmaf(nx[0], ny[0], R);
            }
            const int rb = seg * 8;
            s_E[rb][col] = make_float4(P.x, P.y, Q.x + Q.y, R);

            #pragma unroll
            for (int r = 1; r < 8; r++) {
                const float2 pn = make_float2(nx[r], ny[r]);
                const float2 po = (r < 7) ? make_float2(cx[r - 1], cy[r - 1])
                                          : make_float2(nx[0], ny[0]);
                P = f2add(P, pn);
                P = f2fma(po, neg1, P);
                Q = f2fma(pn, pn, Q);
                const float2 mpo = f2mul(po, neg1);
                Q = f2fma(mpo, po, Q);
                R = fmaf(pn.x, pn.y, R);
                R = fmaf(-po.x, po.y, R);
                s_E[rb + r][col] = make_float4(P.x, P.y, Q.x + Q.y, R);
            }
        }
        // carry = new[2..7]
        #pragma unroll
        for (int j = 0; j < 6; j++) { cx[j] = nx[j + 2]; cy[j] = ny[j + 2]; }

        __syncthreads();   // publish s_E

        // ---- phase 2: horizontal sliding + SSIM on 16 buffer rows ----
        {
            const int gy = ty0 + ((r2 < 8) ? (it * 8 + r2)
                                           : (HALF + it * 8 + (r2 - 8)));
            const unsigned msk = (gy < OUT) ? colmask : 0u;

            float4 ring[7];
            float2 Sp = make_float2(0.f, 0.f);
            float2 Sq = make_float2(0.f, 0.f);
            #pragma unroll
            for (int k = 0; k < WIN; k++) {
                const float4 e = s_E[r2][c0 + k];
                ring[k] = e;
                Sp = f2add(Sp, make_float2(e.x, e.y));
                Sq = f2add(Sq, make_float2(e.z, e.w));
            }

            #pragma unroll
            for (int ph = 0; ph < 4; ph++) {
                const int ci0 = 2 * ph;
                // --- output ci0 ---
                float nm0, dm0;
                {
                    const float2 PP = f2mul(Sp, Sp);
                    const float t1 = Sp.x * Sp.y;
                    const float b1 = PP.x + PP.y;
                    const float A1 = fmaf(t1, 2.0f, C1s);
                    const float B1 = b1 + C1s;
                    const float A2 = fmaf(COV2, fmaf(iw, Sq.y, -t1), C2s);
                    const float B2 = fmaf(COV,  fmaf(iw, Sq.x, -b1), C2s);
                    const bool a = (msk >> ci0) & 1u;
                    nm0 = a ? (A1 * A2) : 0.0f;
                    dm0 = a ? fmaf(B1, B2, epsS) : 1.0f;
                }
                // slide ci0 -> ci0+1 (always valid: ci0 <= 6, c0+ci0+7 < 64
                // except q=7 where compare handles it)
                {
                    const int c = c0 + ci0;
                    if (c + 7 < COLS) {
                        const float4 ne = s_E[r2][c + 7];
                        const float4 oe = ring[ci0];
                        Sp = f2add(Sp, make_float2(ne.x, ne.y));
                        Sp = f2fma(make_float2(oe.x, oe.y), neg1, Sp);
                        Sq = f2add(Sq, make_float2(ne.z, ne.w));
                        Sq = f2fma(make_float2(oe.z, oe.w), neg1, Sq);
                    }
                }
                // --- output ci0+1 ---
                float nm1, dm1;
                {
                    const float2 PP = f2mul(Sp, Sp);
                    const float t1 = Sp.x * Sp.y;
                    const float b1 = PP.x + PP.y;
                    const float A1 = fmaf(t1, 2.0f, C1s);
                    const float B1 = b1 + C1s;
                    const float A2 = fmaf(COV2, fmaf(iw, Sq.y, -t1), C2s);
                    const float B2 = fmaf(COV,  fmaf(iw, Sq.x, -b1), C2s);
                    const bool a = (msk >> (ci0 + 1)) & 1u;
                    nm1 = a ? (A1 * A2) : 0.0f;
                    dm1 = a ? fmaf(B1, B2, epsS) : 1.0f;
                }
                // one reciprocal per pair
                local += __fdividef(fmaf(nm0, dm1, nm1 * dm0), dm0 * dm1);
                // slide ci0+1 -> ci0+2 (skip after last output)
                if (ph < 3) {
                    const int c = c0 + ci0 + 1;
                    if (c + 7 < COLS) {
                        const float4 ne = s_E[r2][c + 7];
                        const float4 oe = ring[ci0 + 1];
                        Sp = f2add(Sp, make_float2(ne.x, ne.y));
                        Sp = f2fma(make_float2(oe.x, oe.y), neg1, Sp);
                        Sq = f2add(Sq, make_float2(ne.z, ne.w));
                        Sq = f2fma(make_float2(oe.z, oe.w), neg1, Sq);
                    }
                }
            }
        }
        __syncthreads();   // protect s_E before next iteration's writes
    }

    // ---------------- Block reduction + fused finalize ----------------------
    #pragma unroll
    for (int off = 16; off > 0; off >>= 1)
        local += __shfl_down_sync(0xffffffffu, local, off);
    if ((tid & 31) == 0) warpsum[tid >> 5] = local;
    __syncthreads();
    if (tid == 0) {
        const float v = warpsum[0] + warpsum[1] + warpsum[2] + warpsum[3];
        atomicAdd(&g_accum, (double)v);
        __threadfence();
        const unsigned done = atomicAdd(&g_count, 1u);
        if (done == NBLOCKS - 1) {
            const double total = atomicAdd(&g_accum, 0.0);
            out[0] = (float)(1.0 - total / NELEM);
            g_accum = 0.0;            // reset for next graph replay
            g_count = 0u;
        }
    }
}

extern "C" void kernel_launch(void* const* d_in, const int* in_sizes, int n_in,
                              void* d_out, int out_size) {
    const float* X  = (const float*)d_in[0];
    const float* Y  = (const float*)d_in[1];
    const float* dr = (const float*)d_in[2];
    const float* w  = (const float*)d_in[3];
    float* out = (float*)d_out;

    dim3 grid(GRID_X, GRID_Y, NIMG);
    ssim_main_kernel<<<grid, 128>>>(X, Y, dr, w, out);
}

// round 15
// speedup vs baseline: 1.8374x; 1.0147x over previous
#include <cuda_runtime.h>
#include <cuda_bf16.h>

// SSIM loss: X,Y (32,8,320,320) fp32, 7x7 uniform box (valid), out = 1 - mean(S)
//
// R14 skeleton + cp.async SMEM-staged prefetch:
//  - next iteration's 16 rows x 64 cols x {X,Y} staged via cp.async.cg
//    (global->shared, no register liveness), issued right after the slide
//    publishes s_E -> overlaps phase 2 + barriers (~1000 cyc) before use.
//  - vertical slide reads rows from SMEM staging (conflict-free LDS.32).
//  - single staging buffer is hazard-free: reads(it) end before sync_b,
//    writes(it+1) issued after sync_b.
//  - TILE_W 56 (tx0 % 4 == 0 for 16B cp.async alignment).
//  - phase 2: R14's ring + hoisted colmask + paired reciprocal.

#define WIN      7
#define IMG      320
#define OUT      314
#define NIMG     256
#define NELEM    25240576.0

#define COLS     64
#define TILE_W   56
#define STRIP    80                  // output rows per block strip
#define HALF     40                  // rows per thread-segment
#define NITER    5                   // iterations of 16 buffer rows (8 per seg)
#define SSTRIDE  (COLS + 1)          // 65 float4 entries per row
#define GRID_X   6
#define GRID_Y   4
#define NBLOCKS  (GRID_X * GRID_Y * NIMG)   // 6144

__device__ double g_accum;
__device__ unsigned int g_count;

// ---- packed f32x2 helpers (sm_103a) ----
__device__ __forceinline__ float2 f2add(float2 a, float2 b) {
    unsigned long long ra = *(unsigned long long*)&a;
    unsigned long long rb = *(unsigned long long*)&b;
    unsigned long long rd;
    asm("add.rn.f32x2 %0, %1, %2;" : "=l"(rd) : "l"(ra), "l"(rb));
    return *(float2*)&rd;
}
__device__ __forceinline__ float2 f2mul(float2 a, float2 b) {
    unsigned long long ra = *(unsigned long long*)&a;
    unsigned long long rb = *(unsigned long long*)&b;
    unsigned long long rd;
    asm("mul.rn.f32x2 %0, %1, %2;" : "=l"(rd) : "l"(ra), "l"(rb));
    return *(float2*)&rd;
}
__device__ __forceinline__ float2 f2fma(float2 a, float2 b, float2 c) {
    unsigned long long ra = *(unsigned long long*)&a;
    unsigned long long rb = *(unsigned long long*)&b;
    unsigned long long rc = *(unsigned long long*)&c;
    unsigned long long rd;
    asm("fma.rn.f32x2 %0, %1, %2, %3;" : "=l"(rd) : "l"(ra), "l"(rb), "l"(rc));
    return *(float2*)&rd;
}

#define CP_ASYNC16(dst, src) \
    asm volatile("cp.async.cg.shared.global [%0], [%1], 16;" \
                 :: "r"(dst), "l"(src) : "memory")
#define CP_COMMIT()  asm volatile("cp.async.commit_group;" ::: "memory")
#define CP_WAIT0()   asm volatile("cp.async.wait_group 0;" ::: "memory")

__global__ __launch_bounds__(128, 8) void ssim_main_kernel(
    const float* __restrict__ X, const float* __restrict__ Y,
    const float* __restrict__ data_range, const float* __restrict__ w,
    float* __restrict__ out)
{
    __shared__ float4 s_E[16][SSTRIDE];   // (sx, sy, sxx+syy, sxy)  16.6 KB
    __shared__ float  sbx[16][COLS];      // staged X rows            4 KB
    __shared__ float  sby[16][COLS];      // staged Y rows            4 KB
    __shared__ float  warpsum[4];

    const int img = blockIdx.z;
    const int tx0 = blockIdx.x * TILE_W;          // multiple of 4 (56)
    const int ty0 = blockIdx.y * STRIP;
    const float* Xb = X + (size_t)img * IMG * IMG;
    const float* Yb = Y + (size_t)img * IMG * IMG;
    const int tid = threadIdx.x;
    const float2 neg1 = make_float2(-1.f, -1.f);

    const unsigned sbx_base = (unsigned)__cvta_generic_to_shared(&sbx[0][0]);
    const unsigned sby_base = (unsigned)__cvta_generic_to_shared(&sby[0][0]);

    // constants for SSIM (rescaled by (1/w)^2)
    const float w0  = w[0];
    const float iw  = 1.0f / w0;                // ~49
    const float dr  = data_range[0];
    const float c1t = 0.01f * dr;
    const float c2t = 0.03f * dr;
    const float C1s = (c1t * c1t) * iw * iw;
    const float C2s = (c2t * c2t) * iw * iw;
    const float COV  = 49.0f / 48.0f;
    const float COV2 = 2.0f * COV;
    const float epsS = 1e-8f * (iw * iw) * (iw * iw);

    // phase-1 coords: thread = (column, segment)
    const int col = tid & (COLS - 1);
    const int seg = tid >> 6;                   // 0..1
    const int gx  = min(tx0 + col, IMG - 1);    // clamped cols feed only
                                                // discarded outputs
    const int base = ty0 + seg * HALF;          // first input row of segment

    // loader coords (cp.async): chunk k of 4 per thread
    const int lrow = tid >> 4;                  // 0..7
    const int lcol4 = (tid & 15) << 2;          // 0,4,..,60
    const int lgc = min(tx0 + lcol4, IMG - 4);  // 16B-aligned, clamped

    // phase-2 coords
    const int r2 = tid & 15;                    // buffer row
    const int q  = tid >> 4;                    // 0..7 column chunk
    const int c0 = q * 8;

    // hoisted column mask (iteration-invariant)
    unsigned colmask = 0u;
    #pragma unroll
    for (int ci = 0; ci < 8; ci++) {
        const int c = c0 + ci;
        if ((c < TILE_W) && (tx0 + c < OUT)) colmask |= (1u << ci);
    }

    // prime carry: input rows base..base+5 (max base=280 -> in-bounds)
    float cx[6], cy[6];
    {
        const float* xp = Xb + (size_t)base * IMG + gx;
        const float* yp = Yb + (size_t)base * IMG + gx;
        #pragma unroll
        for (int j = 0; j < 6; j++) {
            cx[j] = __ldg(xp + j * IMG);
            cy[j] = __ldg(yp + j * IMG);
        }
    }

    // issue staged loads for iteration 0 (rows base+6..base+13 per seg)
    {
        #pragma unroll
        for (int k = 0; k < 4; k++) {
            const int tensor = k >> 1;              // 0,0,1,1
            const int row16 = lrow + ((k & 1) << 3);// rows 0..7 / 8..15
            const int sgl = row16 >> 3;
            const int rl  = row16 & 7;
            const int absr = min(ty0 + sgl * HALF + 6 + rl, IMG - 1);
            const float* src = (tensor ? Yb : Xb) + (size_t)absr * IMG + lgc;
            const unsigned dst = (tensor ? sby_base : sbx_base)
                               + (unsigned)(row16 * COLS + lcol4) * 4u;
            CP_ASYNC16(dst, src);
        }
        CP_COMMIT();
    }

    float local = 0.f;

    #pragma unroll 1
    for (int it = 0; it < NITER; ++it) {
        CP_WAIT0();
        __syncthreads();   // staged rows visible; prev phase2 done (s_E free)

        // ---- vertical slide over 14-row window (carry[6] + staged[8]) ----
        {
            const int rb = seg * 8;
            float2 P = make_float2(0.f, 0.f);
            float2 Q = make_float2(0.f, 0.f);
            float  R = 0.f;
            #pragma unroll
            for (int k = 0; k < 6; k++) {
                const float2 p = make_float2(cx[k], cy[k]);
                P = f2add(P, p);
                Q = f2fma(p, p, Q);
                R = fmaf(cx[k], cy[k], R);
            }
            const float x0 = sbx[rb][col];
            const float y0 = sby[rb][col];
            {
                const float2 p = make_float2(x0, y0);
                P = f2add(P, p);
                Q = f2fma(p, p, Q);
                R = fmaf(x0, y0, R);
            }
            s_E[rb][col] = make_float4(P.x, P.y, Q.x + Q.y, R);

            #pragma unroll
            for (int r = 1; r < 8; r++) {
                const float xn = sbx[rb + r][col];
                const float yn = sby[rb + r][col];
                const float2 pn = make_float2(xn, yn);
                const float2 po = (r < 7) ? make_float2(cx[r - 1], cy[r - 1])
                                          : make_float2(x0, y0);
                P = f2add(P, pn);
                P = f2fma(po, neg1, P);
                Q = f2fma(pn, pn, Q);
                const float2 mpo = f2mul(po, neg1);
                Q = f2fma(mpo, po, Q);
                R = fmaf(pn.x, pn.y, R);
                R = fmaf(-po.x, po.y, R);
                s_E[rb + r][col] = make_float4(P.x, P.y, Q.x + Q.y, R);
                if (r >= 2) { cx[r - 2] = xn; cy[r - 2] = yn; }
            }
        }
        __syncthreads();   // publish s_E; staging reads complete

        // ---- issue staged loads for it+1 (overlaps phase 2 + barriers) ----
        if (it < NITER - 1) {
            #pragma unroll
            for (int k = 0; k < 4; k++) {
                const int tensor = k >> 1;
                const int row16 = lrow + ((k & 1) << 3);
                const int sgl = row16 >> 3;
                const int rl  = row16 & 7;
                const int absr = min(ty0 + sgl * HALF + (it + 1) * 8 + 6 + rl,
                                     IMG - 1);
                const float* src = (tensor ? Yb : Xb) + (size_t)absr * IMG + lgc;
                const unsigned dst = (tensor ? sby_base : sbx_base)
                                   + (unsigned)(row16 * COLS + lcol4) * 4u;
                CP_ASYNC16(dst, src);
            }
            CP_COMMIT();
        }

        // ---- phase 2: horizontal sliding + SSIM on 16 buffer rows ----
        {
            const int gy = ty0 + ((r2 < 8) ? (it * 8 + r2)
                                           : (HALF + it * 8 + (r2 - 8)));
            const unsigned msk = (gy < OUT) ? colmask : 0u;

            float4 ring[7];
            float2 Sp = make_float2(0.f, 0.f);
            float2 Sq = make_float2(0.f, 0.f);
            #pragma unroll
            for (int k = 0; k < WIN; k++) {
                const float4 e = s_E[r2][c0 + k];
                ring[k] = e;
                Sp = f2add(Sp, make_float2(e.x, e.y));
                Sq = f2add(Sq, make_float2(e.z, e.w));
            }

            #pragma unroll
            for (int ph = 0; ph < 4; ph++) {
                const int ci0 = 2 * ph;
                float nm0, dm0;
                {
                    const float2 PP = f2mul(Sp, Sp);
                    const float t1 = Sp.x * Sp.y;
                    const float b1 = PP.x + PP.y;
                    const float A1 = fmaf(t1, 2.0f, C1s);
                    const float B1 = b1 + C1s;
                    const float A2 = fmaf(COV2, fmaf(iw, Sq.y, -t1), C2s);
                    const float B2 = fmaf(COV,  fmaf(iw, Sq.x, -b1), C2s);
                    const bool a = (msk >> ci0) & 1u;
                    nm0 = a ? (A1 * A2) : 0.0f;
                    dm0 = a ? fmaf(B1, B2, epsS) : 1.0f;
                }
                {
                    const int c = c0 + ci0;
                    if (c + 7 < COLS) {
                        const float4 ne = s_E[r2][c + 7];
                        const float4 oe = ring[ci0];
                        Sp = f2add(Sp, make_float2(ne.x, ne.y));
                        Sp = f2fma(make_float2(oe.x, oe.y), neg1, Sp);
                        Sq = f2add(Sq, make_float2(ne.z, ne.w));
                        Sq = f2fma(make_float2(oe.z, oe.w), neg1, Sq);
                    }
                }
                float nm1, dm1;
                {
                    const float2 PP = f2mul(Sp, Sp);
                    const float t1 = Sp.x * Sp.y;
                    const float b1 = PP.x + PP.y;
                    const float A1 = fmaf(t1, 2.0f, C1s);
                    const float B1 = b1 + C1s;
                    const float A2 = fmaf(COV2, fmaf(iw, Sq.y, -t1), C2s);
                    const float B2 = fmaf(COV,  fmaf(iw, Sq.x, -b1), C2s);
                    const bool a = (msk >> (ci0 + 1)) & 1u;
                    nm1 = a ? (A1 * A2) : 0.0f;
                    dm1 = a ? fmaf(B1, B2, epsS) : 1.0f;
                }
                local += __fdividef(fmaf(nm0, dm1, nm1 * dm0), dm0 * dm1);
                if (ph < 3) {
                    const int c = c0 + ci0 + 1;
                    if (c + 7 < COLS) {
                        const float4 ne = s_E[r2][c + 7];
                        const float4 oe = ring[ci0 + 1];
                        Sp = f2add(Sp, make_float2(ne.x, ne.y));
                        Sp = f2fma(make_float2(oe.x, oe.y), neg1, Sp);
                        Sq = f2add(Sq, make_float2(ne.z, ne.w));
                        Sq = f2fma(make_float2(oe.z, oe.w), neg1, Sq);
                    }
                }
            }
        }
    }

    // ---------------- Block reduction + fused finalize ----------------------
    #pragma unroll
    for (int off = 16; off > 0; off >>= 1)
        local += __shfl_down_sync(0xffffffffu, local, off);
    if ((tid & 31) == 0) warpsum[tid >> 5] = local;
    __syncthreads();
    if (tid == 0) {
        const float v = warpsum[0] + warpsum[1] + warpsum[2] + warpsum[3];
        atomicAdd(&g_accum, (double)v);
        __threadfence();
        const unsigned done = atomicAdd(&g_count, 1u);
        if (done == NBLOCKS - 1) {
            const double total = atomicAdd(&g_accum, 0.0);
            out[0] = (float)(1.0 - total / NELEM);
            g_accum = 0.0;            // reset for next graph replay
            g_count = 0u;
        }
    }
}

extern "C" void kernel_launch(void* const* d_in, const int* in_sizes, int n_in,
                              void* d_out, int out_size) {
    const float* X  = (const float*)d_in[0];
    const float* Y  = (const float*)d_in[1];
    const float* dr = (const float*)d_in[2];
    const float* w  = (const float*)d_in[3];
    float* out = (float*)d_out;

    dim3 grid(GRID_X, GRID_Y, NIMG);
    ssim_main_kernel<<<grid, 128>>>(X, Y, dr, w, out);
}